// round 2
// baseline (speedup 1.0000x reference)
#include <cuda_runtime.h>
#include <math.h>

#define B_  512
#define T_  512
#define H_  100
#define DI_ 101
#define DO_ 2

// 104.8 MB scratch for the input projection (allowed: __device__ global)
__device__ float g_xp[(size_t)B_ * T_ * H_];

// ---------------------------------------------------------------------------
// Kernel A: xp[r][j] = sum_i input[r][i] * W_x[j][i] + b[j]
// 256 threads, 16-row tiles, 2x4 microtile per thread (8 warps -> better
// latency hiding than round-1's 4 warps).
// ---------------------------------------------------------------------------
__global__ void __launch_bounds__(256) xp_gemm_kernel(
    const float* __restrict__ inp,   // [B*T, DI]
    const float* __restrict__ Wx,    // [H, DI]
    const float* __restrict__ bias)  // [H]
{
    __shared__ __align__(16) float Wx_s[DI_ * H_];   // transposed: [i][j]
    __shared__ __align__(16) float in_s[DI_ * 16];   // transposed: [i][r]

    const int tid = threadIdx.x;
    const int tx  = tid & 31;   // column quad (active tx < 25 -> cols 4*tx..)
    const int ty  = tid >> 5;   // warp id (0..7) -> rows 2*ty, 2*ty+1

    for (int idx = tid; idx < DI_ * H_; idx += 256) {
        int j = idx / DI_;
        int i = idx - j * DI_;
        Wx_s[i * H_ + j] = Wx[idx];
    }

    float bj[4] = {0.f, 0.f, 0.f, 0.f};
    if (tx < 25) {
#pragma unroll
        for (int c = 0; c < 4; c++) bj[c] = bias[4 * tx + c];
    }

    const int ntiles = (B_ * T_) / 16;
    for (int tile = blockIdx.x; tile < ntiles; tile += gridDim.x) {
        __syncthreads();
        const int rbase = tile * 16;
        for (int idx = tid; idx < 16 * DI_; idx += 256) {
            int r = idx / DI_;
            int i = idx - r * DI_;
            in_s[i * 16 + r] = inp[(size_t)(rbase + r) * DI_ + i];
        }
        __syncthreads();

        if (tx < 25) {
            float acc[2][4];
#pragma unroll
            for (int rr = 0; rr < 2; rr++)
#pragma unroll
                for (int cc = 0; cc < 4; cc++) acc[rr][cc] = bj[cc];

#pragma unroll 8
            for (int i = 0; i < DI_; i++) {
                float2 av = *(const float2*)(in_s + i * 16 + 2 * ty);
                float4 wv = *(const float4*)(Wx_s + i * H_ + 4 * tx);
                acc[0][0] = fmaf(av.x, wv.x, acc[0][0]);
                acc[0][1] = fmaf(av.x, wv.y, acc[0][1]);
                acc[0][2] = fmaf(av.x, wv.z, acc[0][2]);
                acc[0][3] = fmaf(av.x, wv.w, acc[0][3]);
                acc[1][0] = fmaf(av.y, wv.x, acc[1][0]);
                acc[1][1] = fmaf(av.y, wv.y, acc[1][1]);
                acc[1][2] = fmaf(av.y, wv.z, acc[1][2]);
                acc[1][3] = fmaf(av.y, wv.w, acc[1][3]);
            }
#pragma unroll
            for (int rr = 0; rr < 2; rr++) {
                int row = rbase + 2 * ty + rr;
                float4 o;
                o.x = acc[rr][0]; o.y = acc[rr][1]; o.z = acc[rr][2]; o.w = acc[rr][3];
                *(float4*)(g_xp + (size_t)row * H_ + 4 * tx) = o;
            }
        }
    }
}

// ---------------------------------------------------------------------------
// Kernel B: the sequential scan — W_h rows held in REGISTERS.
// 128 CTAs x 128 threads. Thread j (j < 100) owns hidden unit j for ALL 4
// chains of this CTA. W row j lives in 25 float4 registers. h vector for the
// 4 chains is a float4-per-k broadcast out of shared, double-buffered.
// One __syncthreads per step; next step's xp/noise LDGs issued pre-barrier.
// ---------------------------------------------------------------------------
__global__ void __launch_bounds__(128, 1) scan_kernel(
    const float* __restrict__ noise,   // [B, T, H]
    const float* __restrict__ Wh,      // [H, H]
    const float* __restrict__ ah0,     // [H]
    float* __restrict__ hstore)        // [B, T, H]
{
    __shared__ __align__(16) float4 hbuf[2][104];   // [k] -> {h_c0,h_c1,h_c2,h_c3}

    const int j  = threadIdx.x;        // hidden unit (active if < 100)
    const int c0 = blockIdx.x * 4;     // first of 4 chains

    // W row j -> 25 float4 registers (row is 400B, 16B-aligned)
    float4 w4[25];
    if (j < H_) {
        const float4* wrow = (const float4*)(Wh + j * H_);
#pragma unroll
        for (int kk = 0; kk < 25; kk++) w4[kk] = wrow[kk];
    }

    float ah[4] = {0.f, 0.f, 0.f, 0.f};
    if (j < H_) {
        float a0 = ah0[j];
#pragma unroll
        for (int c = 0; c < 4; c++) ah[c] = a0;
        float h0 = tanhf(fmaxf(a0, 0.f));
        hbuf[0][j] = make_float4(h0, h0, h0, h0);
    }

    const size_t rb0 = (size_t)(c0 + 0) * T_;
    const size_t rb1 = (size_t)(c0 + 1) * T_;
    const size_t rb2 = (size_t)(c0 + 2) * T_;
    const size_t rb3 = (size_t)(c0 + 3) * T_;

    // Prefetch t=0 streaming operands
    float xp[4] = {0,0,0,0}, nz[4] = {0,0,0,0};
    if (j < H_) {
        xp[0] = g_xp[rb0 * H_ + j];  nz[0] = noise[rb0 * H_ + j];
        xp[1] = g_xp[rb1 * H_ + j];  nz[1] = noise[rb1 * H_ + j];
        xp[2] = g_xp[rb2 * H_ + j];  nz[2] = noise[rb2 * H_ + j];
        xp[3] = g_xp[rb3 * H_ + j];  nz[3] = noise[rb3 * H_ + j];
    }
    __syncthreads();

    int buf = 0;
    for (int t = 0; t < T_; t++) {
        float acc0 = 0.f, acc1 = 0.f, acc2 = 0.f, acc3 = 0.f;
        const float4* hb = hbuf[buf];

        if (j < H_) {
#pragma unroll
            for (int kk = 0; kk < 25; kk++) {
                float4 w = w4[kk];
                float4 ha = hb[4 * kk + 0];
                float4 hbv = hb[4 * kk + 1];
                float4 hc = hb[4 * kk + 2];
                float4 hd = hb[4 * kk + 3];
                acc0 = fmaf(ha.x,  w.x, acc0);
                acc1 = fmaf(ha.y,  w.x, acc1);
                acc2 = fmaf(ha.z,  w.x, acc2);
                acc3 = fmaf(ha.w,  w.x, acc3);
                acc0 = fmaf(hbv.x, w.y, acc0);
                acc1 = fmaf(hbv.y, w.y, acc1);
                acc2 = fmaf(hbv.z, w.y, acc2);
                acc3 = fmaf(hbv.w, w.y, acc3);
                acc0 = fmaf(hc.x,  w.z, acc0);
                acc1 = fmaf(hc.y,  w.z, acc1);
                acc2 = fmaf(hc.z,  w.z, acc2);
                acc3 = fmaf(hc.w,  w.z, acc3);
                acc0 = fmaf(hd.x,  w.w, acc0);
                acc1 = fmaf(hd.y,  w.w, acc1);
                acc2 = fmaf(hd.z,  w.w, acc2);
                acc3 = fmaf(hd.w,  w.w, acc3);
            }
        }

        float h0 = 0.f, h1 = 0.f, h2 = 0.f, h3 = 0.f;
        if (j < H_) {
            ah[0] = fmaf(0.1f, (acc0 + xp[0]) - ah[0], ah[0]);
            ah[1] = fmaf(0.1f, (acc1 + xp[1]) - ah[1], ah[1]);
            ah[2] = fmaf(0.1f, (acc2 + xp[2]) - ah[2], ah[2]);
            ah[3] = fmaf(0.1f, (acc3 + xp[3]) - ah[3], ah[3]);
            h0 = tanhf(fmaxf(ah[0], 0.f)) + nz[0];
            h1 = tanhf(fmaxf(ah[1], 0.f)) + nz[1];
            h2 = tanhf(fmaxf(ah[2], 0.f)) + nz[2];
            h3 = tanhf(fmaxf(ah[3], 0.f)) + nz[3];
            hbuf[buf ^ 1][j] = make_float4(h0, h1, h2, h3);
            hstore[(rb0 + t) * H_ + j] = h0;
            hstore[(rb1 + t) * H_ + j] = h1;
            hstore[(rb2 + t) * H_ + j] = h2;
            hstore[(rb3 + t) * H_ + j] = h3;

            // Prefetch next step's operands BEFORE the barrier (hides DRAM lat)
            int tn = (t + 1 < T_) ? (t + 1) : (T_ - 1);
            xp[0] = g_xp[(rb0 + tn) * H_ + j];  nz[0] = noise[(rb0 + tn) * H_ + j];
            xp[1] = g_xp[(rb1 + tn) * H_ + j];  nz[1] = noise[(rb1 + tn) * H_ + j];
            xp[2] = g_xp[(rb2 + tn) * H_ + j];  nz[2] = noise[(rb2 + tn) * H_ + j];
            xp[3] = g_xp[(rb3 + tn) * H_ + j];  nz[3] = noise[(rb3 + tn) * H_ + j];
        }
        buf ^= 1;
        __syncthreads();
    }
}

// ---------------------------------------------------------------------------
// Kernel C: output[r][d] = sum_j hstore[r][j] * W_y[d][j]
// ---------------------------------------------------------------------------
__global__ void __launch_bounds__(256) outproj_kernel(
    const float* __restrict__ hst,   // [B*T, H]
    const float* __restrict__ Wy,    // [DO, H]
    float* __restrict__ out)         // [B*T, DO]
{
    __shared__ float wy_s[DO_ * H_];
    const int tid = threadIdx.x;
    for (int idx = tid; idx < DO_ * H_; idx += 256) wy_s[idx] = Wy[idx];
    __syncthreads();

    const int lane = tid & 31;
    const int w    = tid >> 5;
    const size_t row = (size_t)blockIdx.x * 8 + w;

    float a0 = 0.f, a1 = 0.f;
    for (int j = lane; j < H_; j += 32) {
        float h = hst[row * H_ + j];
        a0 = fmaf(h, wy_s[j],      a0);
        a1 = fmaf(h, wy_s[H_ + j], a1);
    }
#pragma unroll
    for (int off = 16; off > 0; off >>= 1) {
        a0 += __shfl_down_sync(0xffffffffu, a0, off);
        a1 += __shfl_down_sync(0xffffffffu, a1, off);
    }
    if (lane == 0) {
        out[row * DO_ + 0] = a0;
        out[row * DO_ + 1] = a1;
    }
}

// ---------------------------------------------------------------------------
extern "C" void kernel_launch(void* const* d_in, const int* in_sizes, int n_in,
                              void* d_out, int out_size)
{
    const float* inp   = (const float*)d_in[0];  // [B,T,DI]
    const float* noise = (const float*)d_in[1];  // [B,T,H]
    const float* Wx    = (const float*)d_in[2];  // [H,DI]
    const float* bias  = (const float*)d_in[3];  // [H]
    const float* Wh    = (const float*)d_in[4];  // [H,H]
    const float* Wy    = (const float*)d_in[5];  // [DO,H]
    const float* ah0   = (const float*)d_in[6];  // [H]

    float* out    = (float*)d_out;                  // [B,T,DO] first
    float* hstore = out + (size_t)B_ * T_ * DO_;    // [B,T,H] second

    xp_gemm_kernel<<<2048, 256>>>(inp, Wx, bias);
    scan_kernel<<<B_ / 4, 128>>>(noise, Wh, ah0, hstore);
    outproj_kernel<<<(B_ * T_) / 8, 256>>>(hstore, Wy, out);
}

// round 3
// speedup vs baseline: 1.2981x; 1.2981x over previous
#include <cuda_runtime.h>
#include <math.h>

#define B_  512
#define T_  512
#define H_  100
#define DI_ 101
#define DO_ 2

// 104.8 MB scratch for the input projection (allowed: __device__ global)
__device__ float g_xp[(size_t)B_ * T_ * H_];

// ---------------------------------------------------------------------------
// Kernel A: xp[r][j] = sum_i input[r][i] * W_x[j][i] + b[j]
// 256 threads, 32-row tiles, 4x4 microtile -> 2B of LDS per FMA (FMA-bound).
// Dynamic smem: Wx transposed [i][j] (40.4KB) + in transposed [i][r] (12.9KB).
// ---------------------------------------------------------------------------
__global__ void __launch_bounds__(256) xp_gemm_kernel(
    const float* __restrict__ inp,   // [B*T, DI]
    const float* __restrict__ Wx,    // [H, DI]
    const float* __restrict__ bias)  // [H]
{
    extern __shared__ __align__(16) float smem[];
    float* Wx_s = smem;              // [i][j]  DI_*H_   = 40400 B
    float* in_s = smem + DI_ * H_;   // [i][r]  DI_*32   = 12928 B

    const int tid = threadIdx.x;
    const int tx  = tid & 31;   // column quad (active tx < 25 -> cols 4*tx..)
    const int ty  = tid >> 5;   // warp id (0..7) -> rows 4*ty .. 4*ty+3

    for (int idx = tid; idx < DI_ * H_; idx += 256) {
        int j = idx / DI_;
        int i = idx - j * DI_;
        Wx_s[i * H_ + j] = Wx[idx];
    }

    float bj[4] = {0.f, 0.f, 0.f, 0.f};
    if (tx < 25) {
#pragma unroll
        for (int c = 0; c < 4; c++) bj[c] = bias[4 * tx + c];
    }

    const int ntiles = (B_ * T_) / 32;   // 8192
    for (int tile = blockIdx.x; tile < ntiles; tile += gridDim.x) {
        __syncthreads();
        const int rbase = tile * 32;
        for (int idx = tid; idx < 32 * DI_; idx += 256) {
            int r = idx / DI_;
            int i = idx - r * DI_;
            in_s[i * 32 + r] = inp[(size_t)(rbase + r) * DI_ + i];
        }
        __syncthreads();

        if (tx < 25) {
            float acc[4][4];
#pragma unroll
            for (int rr = 0; rr < 4; rr++)
#pragma unroll
                for (int cc = 0; cc < 4; cc++) acc[rr][cc] = bj[cc];

#pragma unroll 4
            for (int i = 0; i < DI_; i++) {
                float4 av = *(const float4*)(in_s + i * 32 + 4 * ty);   // broadcast
                float4 wv = *(const float4*)(Wx_s + i * H_ + 4 * tx);
                acc[0][0] = fmaf(av.x, wv.x, acc[0][0]);
                acc[0][1] = fmaf(av.x, wv.y, acc[0][1]);
                acc[0][2] = fmaf(av.x, wv.z, acc[0][2]);
                acc[0][3] = fmaf(av.x, wv.w, acc[0][3]);
                acc[1][0] = fmaf(av.y, wv.x, acc[1][0]);
                acc[1][1] = fmaf(av.y, wv.y, acc[1][1]);
                acc[1][2] = fmaf(av.y, wv.z, acc[1][2]);
                acc[1][3] = fmaf(av.y, wv.w, acc[1][3]);
                acc[2][0] = fmaf(av.z, wv.x, acc[2][0]);
                acc[2][1] = fmaf(av.z, wv.y, acc[2][1]);
                acc[2][2] = fmaf(av.z, wv.z, acc[2][2]);
                acc[2][3] = fmaf(av.z, wv.w, acc[2][3]);
                acc[3][0] = fmaf(av.w, wv.x, acc[3][0]);
                acc[3][1] = fmaf(av.w, wv.y, acc[3][1]);
                acc[3][2] = fmaf(av.w, wv.z, acc[3][2]);
                acc[3][3] = fmaf(av.w, wv.w, acc[3][3]);
            }
#pragma unroll
            for (int rr = 0; rr < 4; rr++) {
                int row = rbase + 4 * ty + rr;
                float4 o;
                o.x = acc[rr][0]; o.y = acc[rr][1]; o.z = acc[rr][2]; o.w = acc[rr][3];
                *(float4*)(g_xp + (size_t)row * H_ + 4 * tx) = o;
            }
        }
    }
}

// ---------------------------------------------------------------------------
// Kernel B: sequential scan. 128 CTAs x 256 threads (2 warps per SMSP).
// Group g (tid>>7) owns chains {4*blk+2g, 4*blk+2g+1}. Within a group,
// thread = (warp w, lane) -> j = 25*w + lane (lane<25), so all 4 SMSPs get
// equal FFMA load. W row j lives in 50 float2 registers; h double-buffered
// in shared as float2 per (group, k), read as float4 (2 k's at once).
// One __syncthreads per step; next step's xp/noise prefetched pre-barrier.
// ---------------------------------------------------------------------------
__global__ void __launch_bounds__(256, 1) scan_kernel(
    const float* __restrict__ noise,   // [B, T, H]
    const float* __restrict__ Wh,      // [H, H]
    const float* __restrict__ ah0,     // [H]
    float* __restrict__ hstore)        // [B, T, H]
{
    __shared__ __align__(16) float2 hb[2][2][104];   // [buf][group][k] -> (h_c0, h_c1)

    const int tid  = threadIdx.x;
    const int lane = tid & 31;
    const int w    = (tid >> 5) & 3;
    const int g    = tid >> 7;                 // 0 or 1
    const int j    = 25 * w + lane;            // hidden unit
    const bool act = lane < 25;
    const int cb   = blockIdx.x * 4 + 2 * g;   // first chain of this group

    // W row j -> 50 float2 registers
    float2 w2[50];
    if (act) {
        const float2* wr = (const float2*)(Wh + j * H_);
#pragma unroll
        for (int kk = 0; kk < 50; kk++) w2[kk] = wr[kk];
    }

    float ahx = 0.f, ahy = 0.f;
    if (act) {
        float a0 = ah0[j];
        ahx = a0; ahy = a0;
        float h0 = tanhf(fmaxf(a0, 0.f));
        hb[0][g][j] = make_float2(h0, h0);
    }

    const size_t r0 = (size_t)(cb + 0) * T_;
    const size_t r1 = (size_t)(cb + 1) * T_;

    float xp0 = 0.f, xp1 = 0.f, nz0 = 0.f, nz1 = 0.f;
    if (act) {
        xp0 = g_xp[r0 * H_ + j];  nz0 = noise[r0 * H_ + j];
        xp1 = g_xp[r1 * H_ + j];  nz1 = noise[r1 * H_ + j];
    }
    __syncthreads();

    int buf = 0;
    for (int t = 0; t < T_; t++) {
        // Prefetch next step's streaming operands (hide DRAM latency)
        const int tn = (t + 1 < T_) ? (t + 1) : (T_ - 1);
        float pxp0 = 0.f, pxp1 = 0.f, pnz0 = 0.f, pnz1 = 0.f;
        if (act) {
            pxp0 = g_xp[(r0 + tn) * H_ + j];  pnz0 = noise[(r0 + tn) * H_ + j];
            pxp1 = g_xp[(r1 + tn) * H_ + j];  pnz1 = noise[(r1 + tn) * H_ + j];
        }

        if (act) {
            const float4* hp = (const float4*)hb[buf][g];
            float acc0 = 0.f, acc1 = 0.f;
#pragma unroll
            for (int kk = 0; kk < 50; kk++) {
                float4 hv = hp[kk];          // broadcast: k=2kk (c0,c1), k=2kk+1 (c0,c1)
                float2 wv = w2[kk];
                acc0 = fmaf(hv.x, wv.x, acc0);
                acc1 = fmaf(hv.y, wv.x, acc1);
                acc0 = fmaf(hv.z, wv.y, acc0);
                acc1 = fmaf(hv.w, wv.y, acc1);
            }
            ahx = fmaf(0.1f, (acc0 + xp0) - ahx, ahx);
            ahy = fmaf(0.1f, (acc1 + xp1) - ahy, ahy);
            float h0 = tanhf(fmaxf(ahx, 0.f)) + nz0;
            float h1 = tanhf(fmaxf(ahy, 0.f)) + nz1;
            hb[buf ^ 1][g][j] = make_float2(h0, h1);
            hstore[(r0 + t) * H_ + j] = h0;
            hstore[(r1 + t) * H_ + j] = h1;
        }
        xp0 = pxp0; xp1 = pxp1; nz0 = pnz0; nz1 = pnz1;
        buf ^= 1;
        __syncthreads();
    }
}

// ---------------------------------------------------------------------------
// Kernel C: output[r][d] = sum_j hstore[r][j] * W_y[d][j]
// ---------------------------------------------------------------------------
__global__ void __launch_bounds__(256) outproj_kernel(
    const float* __restrict__ hst,   // [B*T, H]
    const float* __restrict__ Wy,    // [DO, H]
    float* __restrict__ out)         // [B*T, DO]
{
    __shared__ float wy_s[DO_ * H_];
    const int tid = threadIdx.x;
    for (int idx = tid; idx < DO_ * H_; idx += 256) wy_s[idx] = Wy[idx];
    __syncthreads();

    const int lane = tid & 31;
    const int w    = tid >> 5;
    const size_t row = (size_t)blockIdx.x * 8 + w;

    float a0 = 0.f, a1 = 0.f;
    for (int j = lane; j < H_; j += 32) {
        float h = hst[row * H_ + j];
        a0 = fmaf(h, wy_s[j],      a0);
        a1 = fmaf(h, wy_s[H_ + j], a1);
    }
#pragma unroll
    for (int off = 16; off > 0; off >>= 1) {
        a0 += __shfl_down_sync(0xffffffffu, a0, off);
        a1 += __shfl_down_sync(0xffffffffu, a1, off);
    }
    if (lane == 0) {
        out[row * DO_ + 0] = a0;
        out[row * DO_ + 1] = a1;
    }
}

// ---------------------------------------------------------------------------
extern "C" void kernel_launch(void* const* d_in, const int* in_sizes, int n_in,
                              void* d_out, int out_size)
{
    const float* inp   = (const float*)d_in[0];  // [B,T,DI]
    const float* noise = (const float*)d_in[1];  // [B,T,H]
    const float* Wx    = (const float*)d_in[2];  // [H,DI]
    const float* bias  = (const float*)d_in[3];  // [H]
    const float* Wh    = (const float*)d_in[4];  // [H,H]
    const float* Wy    = (const float*)d_in[5];  // [DO,H]
    const float* ah0   = (const float*)d_in[6];  // [H]

    float* out    = (float*)d_out;                  // [B,T,DO] first
    float* hstore = out + (size_t)B_ * T_ * DO_;    // [B,T,H] second

    const int xp_smem = (DI_ * H_ + DI_ * 32) * (int)sizeof(float);  // 53328 B
    static int attr_done = 0;
    if (!attr_done) {
        cudaFuncSetAttribute(xp_gemm_kernel,
                             cudaFuncAttributeMaxDynamicSharedMemorySize, xp_smem);
        attr_done = 1;
    }

    xp_gemm_kernel<<<1024, 256, xp_smem>>>(inp, Wx, bias);
    scan_kernel<<<B_ / 4, 256>>>(noise, Wh, ah0, hstore);
    outproj_kernel<<<(B_ * T_) / 8, 256>>>(hstore, Wy, out);
}

// round 4
// speedup vs baseline: 1.5523x; 1.1959x over previous
#include <cuda_runtime.h>
#include <math.h>

#define B_  512
#define T_  512
#define H_  100
#define DI_ 101
#define DO_ 2

typedef unsigned long long ull;

__device__ float g_xp[(size_t)B_ * T_ * H_];

__device__ __forceinline__ ull fma2(ull a, ull b, ull c) {
    ull d;
    asm("fma.rn.f32x2 %0, %1, %2, %3;" : "=l"(d) : "l"(a), "l"(b), "l"(c));
    return d;
}
__device__ __forceinline__ ull dup2(float a) {
    ull d;
    asm("mov.b64 %0, {%1, %1};" : "=l"(d) : "f"(a));
    return d;
}
__device__ __forceinline__ float2 u2f(ull v) {
    float2 f;
    asm("mov.b64 {%0, %1}, %2;" : "=f"(f.x), "=f"(f.y) : "l"(v));
    return f;
}

// ---------------------------------------------------------------------------
// Kernel A: xp[r][j] = sum_i input[r][i] * W_x[j][i] + b[j]
// 256 threads, 64-row tiles, 8x4 microtile, FFMA2 (cols packed in pairs).
// in_s stride 68 (4-way STS conflict instead of 32-way at stride 64/32).
// ---------------------------------------------------------------------------
#define INS_STRIDE 68
__global__ void __launch_bounds__(256) xp_gemm_kernel(
    const float* __restrict__ inp,   // [B*T, DI]
    const float* __restrict__ Wx,    // [H, DI]
    const float* __restrict__ bias)  // [H]
{
    extern __shared__ __align__(16) float smem[];
    float* Wx_s = smem;                 // [i][j]  DI_*H_ floats
    float* in_s = smem + DI_ * H_;      // [i][r]  DI_*INS_STRIDE floats

    const int tid = threadIdx.x;
    const int tx  = tid & 31;   // col quad (active tx < 25 -> cols 4*tx..)
    const int ty  = tid >> 5;   // warp id (0..7) -> rows 8*ty .. 8*ty+7

    for (int idx = tid; idx < DI_ * H_; idx += 256) {
        int j = idx / DI_;
        int i = idx - j * DI_;
        Wx_s[i * H_ + j] = Wx[idx];
    }

    ull bj01 = 0, bj23 = 0;
    if (tx < 25) {
        const ull* bp = (const ull*)(bias + 4 * tx);
        bj01 = bp[0];
        bj23 = bp[1];
    }

    const int ntiles = (B_ * T_) / 64;   // 4096
    for (int tile = blockIdx.x; tile < ntiles; tile += gridDim.x) {
        __syncthreads();
        const int rbase = tile * 64;
        for (int idx = tid; idx < 64 * DI_; idx += 256) {
            int r = idx / DI_;
            int i = idx - r * DI_;
            in_s[i * INS_STRIDE + r] = inp[(size_t)(rbase + r) * DI_ + i];
        }
        __syncthreads();

        if (tx < 25) {
            ull acc[8][2];
#pragma unroll
            for (int rr = 0; rr < 8; rr++) { acc[rr][0] = bj01; acc[rr][1] = bj23; }

#pragma unroll 4
            for (int i = 0; i < DI_; i++) {
                float4 a0 = *(const float4*)(in_s + i * INS_STRIDE + 8 * ty);
                float4 a1 = *(const float4*)(in_s + i * INS_STRIDE + 8 * ty + 4);
                ulonglong2 wv = *(const ulonglong2*)(Wx_s + i * H_ + 4 * tx);
                ull d;
                d = dup2(a0.x); acc[0][0] = fma2(d, wv.x, acc[0][0]); acc[0][1] = fma2(d, wv.y, acc[0][1]);
                d = dup2(a0.y); acc[1][0] = fma2(d, wv.x, acc[1][0]); acc[1][1] = fma2(d, wv.y, acc[1][1]);
                d = dup2(a0.z); acc[2][0] = fma2(d, wv.x, acc[2][0]); acc[2][1] = fma2(d, wv.y, acc[2][1]);
                d = dup2(a0.w); acc[3][0] = fma2(d, wv.x, acc[3][0]); acc[3][1] = fma2(d, wv.y, acc[3][1]);
                d = dup2(a1.x); acc[4][0] = fma2(d, wv.x, acc[4][0]); acc[4][1] = fma2(d, wv.y, acc[4][1]);
                d = dup2(a1.y); acc[5][0] = fma2(d, wv.x, acc[5][0]); acc[5][1] = fma2(d, wv.y, acc[5][1]);
                d = dup2(a1.z); acc[6][0] = fma2(d, wv.x, acc[6][0]); acc[6][1] = fma2(d, wv.y, acc[6][1]);
                d = dup2(a1.w); acc[7][0] = fma2(d, wv.x, acc[7][0]); acc[7][1] = fma2(d, wv.y, acc[7][1]);
            }
#pragma unroll
            for (int rr = 0; rr < 8; rr++) {
                int row = rbase + 8 * ty + rr;
                ull* op = (ull*)(g_xp + (size_t)row * H_ + 4 * tx);
                op[0] = acc[rr][0];
                op[1] = acc[rr][1];
            }
        }
    }
}

// ---------------------------------------------------------------------------
// Kernel B: sequential scan with FFMA2 packed over k.
// 128 CTAs x 256 threads. Group g = tid>>7 owns chains {4*blk+2g, +1}.
// j = 25*w + lane (lane<25) balances all 4 SMSPs. W row j held as 50 packed
// b64 regs. h stored chain-major in smem so ulonglong2 broadcast loads give
// packed (h_k, h_k+1) pairs directly. 4 independent packed accumulators.
// ---------------------------------------------------------------------------
__global__ void __launch_bounds__(256, 1) scan_kernel(
    const float* __restrict__ noise,   // [B, T, H]
    const float* __restrict__ Wh,      // [H, H]
    const float* __restrict__ ah0,     // [H]
    float* __restrict__ hstore)        // [B, T, H]
{
    __shared__ __align__(16) float hs[2][4][104];   // [buf][chain_local][k]

    const int tid  = threadIdx.x;
    const int lane = tid & 31;
    const int w    = (tid >> 5) & 3;
    const int g    = tid >> 7;                 // 0 or 1
    const int j    = 25 * w + lane;            // hidden unit
    const bool act = lane < 25;
    const int cb   = blockIdx.x * 4 + 2 * g;   // first chain of this group

    // W row j -> 50 packed b64 regs (pairs over k)
    ull wk[50];
    if (act) {
        const ulonglong2* wr = (const ulonglong2*)(Wh + j * H_);   // 400B, 16B-aligned
#pragma unroll
        for (int kk = 0; kk < 25; kk++) {
            ulonglong2 v = wr[kk];
            wk[2 * kk]     = v.x;
            wk[2 * kk + 1] = v.y;
        }
    }

    float ahx = 0.f, ahy = 0.f;
    if (act) {
        float a0 = ah0[j];
        ahx = a0; ahy = a0;
        float h0 = tanhf(fmaxf(a0, 0.f));
        hs[0][2 * g][j]     = h0;
        hs[0][2 * g + 1][j] = h0;
    }

    const size_t r0 = (size_t)(cb + 0) * T_;
    const size_t r1 = (size_t)(cb + 1) * T_;

    float xp0 = 0.f, xp1 = 0.f, nz0 = 0.f, nz1 = 0.f;
    if (act) {
        xp0 = g_xp[r0 * H_ + j];  nz0 = noise[r0 * H_ + j];
        xp1 = g_xp[r1 * H_ + j];  nz1 = noise[r1 * H_ + j];
    }
    __syncthreads();

    int buf = 0;
    for (int t = 0; t < T_; t++) {
        // Prefetch next step's streaming operands
        const int tn = (t + 1 < T_) ? (t + 1) : (T_ - 1);
        float pxp0 = 0.f, pxp1 = 0.f, pnz0 = 0.f, pnz1 = 0.f;
        if (act) {
            pxp0 = g_xp[(r0 + tn) * H_ + j];  pnz0 = noise[(r0 + tn) * H_ + j];
            pxp1 = g_xp[(r1 + tn) * H_ + j];  pnz1 = noise[(r1 + tn) * H_ + j];
        }

        if (act) {
            const ulonglong2* h0p = (const ulonglong2*)hs[buf][2 * g];
            const ulonglong2* h1p = (const ulonglong2*)hs[buf][2 * g + 1];
            ull acc00 = 0, acc01 = 0, acc10 = 0, acc11 = 0;  // 0.0f|0.0f packed
#pragma unroll
            for (int kk = 0; kk < 25; kk++) {
                ulonglong2 ha = h0p[kk];   // (h_4kk,h_4kk+1),(h_4kk+2,h_4kk+3) chain0
                ulonglong2 hb = h1p[kk];   // chain1
                acc00 = fma2(ha.x, wk[2 * kk],     acc00);
                acc01 = fma2(ha.y, wk[2 * kk + 1], acc01);
                acc10 = fma2(hb.x, wk[2 * kk],     acc10);
                acc11 = fma2(hb.y, wk[2 * kk + 1], acc11);
            }
            float2 s00 = u2f(acc00), s01 = u2f(acc01);
            float2 s10 = u2f(acc10), s11 = u2f(acc11);
            float sum0 = (s00.x + s00.y) + (s01.x + s01.y);
            float sum1 = (s10.x + s10.y) + (s11.x + s11.y);

            ahx = fmaf(0.1f, (sum0 + xp0) - ahx, ahx);
            ahy = fmaf(0.1f, (sum1 + xp1) - ahy, ahy);
            float h0 = tanhf(fmaxf(ahx, 0.f)) + nz0;
            float h1 = tanhf(fmaxf(ahy, 0.f)) + nz1;
            hs[buf ^ 1][2 * g][j]     = h0;
            hs[buf ^ 1][2 * g + 1][j] = h1;
            hstore[(r0 + t) * H_ + j] = h0;
            hstore[(r1 + t) * H_ + j] = h1;
        }
        xp0 = pxp0; xp1 = pxp1; nz0 = pnz0; nz1 = pnz1;
        buf ^= 1;
        __syncthreads();
    }
}

// ---------------------------------------------------------------------------
// Kernel C: output[r][d] = sum_j hstore[r][j] * W_y[d][j]
// ---------------------------------------------------------------------------
__global__ void __launch_bounds__(256) outproj_kernel(
    const float* __restrict__ hst,   // [B*T, H]
    const float* __restrict__ Wy,    // [DO, H]
    float* __restrict__ out)         // [B*T, DO]
{
    __shared__ float wy_s[DO_ * H_];
    const int tid = threadIdx.x;
    for (int idx = tid; idx < DO_ * H_; idx += 256) wy_s[idx] = Wy[idx];
    __syncthreads();

    const int lane = tid & 31;
    const int w    = tid >> 5;
    const size_t row = (size_t)blockIdx.x * 8 + w;

    float a0 = 0.f, a1 = 0.f;
    for (int j = lane; j < H_; j += 32) {
        float h = hst[row * H_ + j];
        a0 = fmaf(h, wy_s[j],      a0);
        a1 = fmaf(h, wy_s[H_ + j], a1);
    }
#pragma unroll
    for (int off = 16; off > 0; off >>= 1) {
        a0 += __shfl_down_sync(0xffffffffu, a0, off);
        a1 += __shfl_down_sync(0xffffffffu, a1, off);
    }
    if (lane == 0) {
        out[row * DO_ + 0] = a0;
        out[row * DO_ + 1] = a1;
    }
}

// ---------------------------------------------------------------------------
extern "C" void kernel_launch(void* const* d_in, const int* in_sizes, int n_in,
                              void* d_out, int out_size)
{
    const float* inp   = (const float*)d_in[0];  // [B,T,DI]
    const float* noise = (const float*)d_in[1];  // [B,T,H]
    const float* Wx    = (const float*)d_in[2];  // [H,DI]
    const float* bias  = (const float*)d_in[3];  // [H]
    const float* Wh    = (const float*)d_in[4];  // [H,H]
    const float* Wy    = (const float*)d_in[5];  // [DO,H]
    const float* ah0   = (const float*)d_in[6];  // [H]

    float* out    = (float*)d_out;                  // [B,T,DO] first
    float* hstore = out + (size_t)B_ * T_ * DO_;    // [B,T,H] second

    const int xp_smem = (DI_ * H_ + DI_ * INS_STRIDE) * (int)sizeof(float);  // 67872 B
    static int attr_done = 0;
    if (!attr_done) {
        cudaFuncSetAttribute(xp_gemm_kernel,
                             cudaFuncAttributeMaxDynamicSharedMemorySize, xp_smem);
        attr_done = 1;
    }

    xp_gemm_kernel<<<1024, 256, xp_smem>>>(inp, Wx, bias);
    scan_kernel<<<B_ / 4, 256>>>(noise, Wh, ah0, hstore);
    outproj_kernel<<<(B_ * T_) / 8, 256>>>(hstore, Wy, out);
}

// round 5
// speedup vs baseline: 1.6231x; 1.0456x over previous
#include <cuda_runtime.h>
#include <math.h>

#define B_  512
#define T_  512
#define H_  100
#define DI_ 101
#define DO_ 2

typedef unsigned long long ull;

__device__ float g_xp[(size_t)B_ * T_ * H_];

__device__ __forceinline__ ull fma2(ull a, ull b, ull c) {
    ull d;
    asm("fma.rn.f32x2 %0, %1, %2, %3;" : "=l"(d) : "l"(a), "l"(b), "l"(c));
    return d;
}
__device__ __forceinline__ ull dup2(float a) {
    ull d;
    asm("mov.b64 %0, {%1, %1};" : "=l"(d) : "f"(a));
    return d;
}
__device__ __forceinline__ float2 u2f(ull v) {
    float2 f;
    asm("mov.b64 {%0, %1}, %2;" : "=f"(f.x), "=f"(f.y) : "l"(v));
    return f;
}

// ---------------------------------------------------------------------------
// Kernel A: xp[r][j] = sum_i input[r][i] * W_x[j][i] + b[j]
// 256 threads, 64-row tiles, 8x4 microtile. ROWS packed in FFMA2 pairs
// (row pairs come straight out of in_s as b64 — no dup). Only 4 dup2/i for w.
// 23 issue slots per i per warp (was 27).
// ---------------------------------------------------------------------------
#define INS_STRIDE 68
__global__ void __launch_bounds__(256) xp_gemm_kernel(
    const float* __restrict__ inp,   // [B*T, DI]
    const float* __restrict__ Wx,    // [H, DI]
    const float* __restrict__ bias)  // [H]
{
    extern __shared__ __align__(16) float smem[];
    float* Wx_s = smem;                 // [i][j]  DI_*H_ floats
    float* in_s = smem + DI_ * H_;      // [i][r]  DI_*INS_STRIDE floats

    const int tid = threadIdx.x;
    const int tx  = tid & 31;   // col quad (active tx < 25 -> cols 4*tx..)
    const int ty  = tid >> 5;   // warp id (0..7) -> rows 8*ty .. 8*ty+7

    for (int idx = tid; idx < DI_ * H_; idx += 256) {
        int j = idx / DI_;
        int i = idx - j * DI_;
        Wx_s[i * H_ + j] = Wx[idx];
    }

    float bv[4] = {0.f, 0.f, 0.f, 0.f};
    if (tx < 25) {
#pragma unroll
        for (int c = 0; c < 4; c++) bv[c] = bias[4 * tx + c];
    }

    const int ntiles = (B_ * T_) / 64;   // 4096
    for (int tile = blockIdx.x; tile < ntiles; tile += gridDim.x) {
        __syncthreads();
        const int rbase = tile * 64;
        for (int idx = tid; idx < 64 * DI_; idx += 256) {
            int r = idx / DI_;
            int i = idx - r * DI_;
            in_s[i * INS_STRIDE + r] = inp[(size_t)(rbase + r) * DI_ + i];
        }
        __syncthreads();

        if (tx < 25) {
            // acc[p][c]: packed over row pair p (rows 2p, 2p+1 of the 8), col c
            ull acc[4][4];
#pragma unroll
            for (int p = 0; p < 4; p++)
#pragma unroll
                for (int c = 0; c < 4; c++) acc[p][c] = dup2(bv[c]);

#pragma unroll 4
            for (int i = 0; i < DI_; i++) {
                ulonglong2 ap0 = *(const ulonglong2*)(in_s + i * INS_STRIDE + 8 * ty);     // rows 0-3
                ulonglong2 ap1 = *(const ulonglong2*)(in_s + i * INS_STRIDE + 8 * ty + 4); // rows 4-7
                float4 wv = *(const float4*)(Wx_s + i * H_ + 4 * tx);
                ull w0 = dup2(wv.x), w1 = dup2(wv.y), w2 = dup2(wv.z), w3 = dup2(wv.w);
                acc[0][0] = fma2(ap0.x, w0, acc[0][0]);
                acc[0][1] = fma2(ap0.x, w1, acc[0][1]);
                acc[0][2] = fma2(ap0.x, w2, acc[0][2]);
                acc[0][3] = fma2(ap0.x, w3, acc[0][3]);
                acc[1][0] = fma2(ap0.y, w0, acc[1][0]);
                acc[1][1] = fma2(ap0.y, w1, acc[1][1]);
                acc[1][2] = fma2(ap0.y, w2, acc[1][2]);
                acc[1][3] = fma2(ap0.y, w3, acc[1][3]);
                acc[2][0] = fma2(ap1.x, w0, acc[2][0]);
                acc[2][1] = fma2(ap1.x, w1, acc[2][1]);
                acc[2][2] = fma2(ap1.x, w2, acc[2][2]);
                acc[2][3] = fma2(ap1.x, w3, acc[2][3]);
                acc[3][0] = fma2(ap1.y, w0, acc[3][0]);
                acc[3][1] = fma2(ap1.y, w1, acc[3][1]);
                acc[3][2] = fma2(ap1.y, w2, acc[3][2]);
                acc[3][3] = fma2(ap1.y, w3, acc[3][3]);
            }
#pragma unroll
            for (int p = 0; p < 4; p++) {
                float2 c0 = u2f(acc[p][0]);
                float2 c1 = u2f(acc[p][1]);
                float2 c2 = u2f(acc[p][2]);
                float2 c3 = u2f(acc[p][3]);
                int re = rbase + 8 * ty + 2 * p;
                float4 oe; oe.x = c0.x; oe.y = c1.x; oe.z = c2.x; oe.w = c3.x;
                float4 oo; oo.x = c0.y; oo.y = c1.y; oo.z = c2.y; oo.w = c3.y;
                *(float4*)(g_xp + (size_t)re * H_ + 4 * tx)       = oe;
                *(float4*)(g_xp + (size_t)(re + 1) * H_ + 4 * tx) = oo;
            }
        }
    }
}

// ---------------------------------------------------------------------------
// Kernel B: sequential scan. 256 CTAs x 128 threads, 2 chains per CTA,
// 2 CTAs per SM with INDEPENDENT barriers (one CTA's FFMA2 fills the other's
// tanh/barrier tail). j = 25*w + lane. W row in 50 packed b64 regs.
// h in shared as float4 per k-pair: (h_2k^c0, h_2k+1^c0, h_2k^c1, h_2k+1^c1).
// 4 independent packed accumulators; xp/noise prefetched 2 steps ahead.
// ---------------------------------------------------------------------------
__global__ void __launch_bounds__(128, 2) scan_kernel(
    const float* __restrict__ noise,   // [B, T, H]
    const float* __restrict__ Wh,      // [H, H]
    const float* __restrict__ ah0,     // [H]
    float* __restrict__ hstore)        // [B, T, H]
{
    __shared__ __align__(16) float4 hp[2][52];   // [buf][kpair]

    const int tid  = threadIdx.x;
    const int lane = tid & 31;
    const int w    = tid >> 5;             // 0..3
    const int j    = 25 * w + lane;        // hidden unit
    const bool act = lane < 25;
    const int c0   = blockIdx.x * 2;

    // W row j -> 50 packed b64 regs
    ull wk[50];
    if (act) {
        const ulonglong2* wr = (const ulonglong2*)(Wh + j * H_);
#pragma unroll
        for (int kk = 0; kk < 25; kk++) {
            ulonglong2 v = wr[kk];
            wk[2 * kk]     = v.x;
            wk[2 * kk + 1] = v.y;
        }
    }

    float ahx = 0.f, ahy = 0.f;
    if (act) {
        float a0 = ah0[j];
        ahx = a0; ahy = a0;
        float h0 = tanhf(fmaxf(a0, 0.f));
        float* hb = (float*)&hp[0][j >> 1];
        hb[(j & 1)]     = h0;   // chain 0
        hb[2 + (j & 1)] = h0;   // chain 1
    }

    const size_t r0 = (size_t)(c0 + 0) * T_;
    const size_t r1 = (size_t)(c0 + 1) * T_;

    // Prefetch ring, depth 2
    float xc0 = 0.f, xc1 = 0.f, nc0 = 0.f, nc1 = 0.f;   // for t
    float xn0 = 0.f, xn1 = 0.f, nn0 = 0.f, nn1 = 0.f;   // for t+1
    if (act) {
        xc0 = g_xp[r0 * H_ + j];        nc0 = noise[r0 * H_ + j];
        xc1 = g_xp[r1 * H_ + j];        nc1 = noise[r1 * H_ + j];
        xn0 = g_xp[(r0 + 1) * H_ + j];  nn0 = noise[(r0 + 1) * H_ + j];
        xn1 = g_xp[(r1 + 1) * H_ + j];  nn1 = noise[(r1 + 1) * H_ + j];
    }
    __syncthreads();

    int buf = 0;
    for (int t = 0; t < T_; t++) {
        // Prefetch t+2 (two steps ahead -> DRAM latency fully covered)
        const int tn = (t + 2 < T_) ? (t + 2) : (T_ - 1);
        float px0 = 0.f, px1 = 0.f, pn0 = 0.f, pn1 = 0.f;
        if (act) {
            px0 = g_xp[(r0 + tn) * H_ + j];  pn0 = noise[(r0 + tn) * H_ + j];
            px1 = g_xp[(r1 + tn) * H_ + j];  pn1 = noise[(r1 + tn) * H_ + j];
        }

        if (act) {
            const ulonglong2* h4 = (const ulonglong2*)hp[buf];
            ull a0a = 0, a0b = 0, a1a = 0, a1b = 0;
#pragma unroll
            for (int kk = 0; kk < 50; kk += 2) {
                ulonglong2 va = h4[kk];       // (c0 pair | c1 pair) for k=2kk,2kk+1
                ulonglong2 vb = h4[kk + 1];
                a0a = fma2(va.x, wk[kk],     a0a);
                a1a = fma2(va.y, wk[kk],     a1a);
                a0b = fma2(vb.x, wk[kk + 1], a0b);
                a1b = fma2(vb.y, wk[kk + 1], a1b);
            }
            float2 s0a = u2f(a0a), s0b = u2f(a0b);
            float2 s1a = u2f(a1a), s1b = u2f(a1b);
            float sum0 = (s0a.x + s0a.y) + (s0b.x + s0b.y);
            float sum1 = (s1a.x + s1a.y) + (s1b.x + s1b.y);

            ahx = fmaf(0.1f, (sum0 + xc0) - ahx, ahx);
            ahy = fmaf(0.1f, (sum1 + xc1) - ahy, ahy);
            float h0 = tanhf(fmaxf(ahx, 0.f)) + nc0;
            float h1 = tanhf(fmaxf(ahy, 0.f)) + nc1;
            float* hb = (float*)&hp[buf ^ 1][j >> 1];
            hb[(j & 1)]     = h0;
            hb[2 + (j & 1)] = h1;
            hstore[(r0 + t) * H_ + j] = h0;
            hstore[(r1 + t) * H_ + j] = h1;
        }
        // rotate prefetch ring
        xc0 = xn0; xc1 = xn1; nc0 = nn0; nc1 = nn1;
        xn0 = px0; xn1 = px1; nn0 = pn0; nn1 = pn1;
        buf ^= 1;
        __syncthreads();
    }
}

// ---------------------------------------------------------------------------
// Kernel C: output[r][d] = sum_j hstore[r][j] * W_y[d][j]
// ---------------------------------------------------------------------------
__global__ void __launch_bounds__(256) outproj_kernel(
    const float* __restrict__ hst,   // [B*T, H]
    const float* __restrict__ Wy,    // [DO, H]
    float* __restrict__ out)         // [B*T, DO]
{
    __shared__ float wy_s[DO_ * H_];
    const int tid = threadIdx.x;
    for (int idx = tid; idx < DO_ * H_; idx += 256) wy_s[idx] = Wy[idx];
    __syncthreads();

    const int lane = tid & 31;
    const int w    = tid >> 5;
    const size_t row = (size_t)blockIdx.x * 8 + w;

    float a0 = 0.f, a1 = 0.f;
    for (int j = lane; j < H_; j += 32) {
        float h = hst[row * H_ + j];
        a0 = fmaf(h, wy_s[j],      a0);
        a1 = fmaf(h, wy_s[H_ + j], a1);
    }
#pragma unroll
    for (int off = 16; off > 0; off >>= 1) {
        a0 += __shfl_down_sync(0xffffffffu, a0, off);
        a1 += __shfl_down_sync(0xffffffffu, a1, off);
    }
    if (lane == 0) {
        out[row * DO_ + 0] = a0;
        out[row * DO_ + 1] = a1;
    }
}

// ---------------------------------------------------------------------------
extern "C" void kernel_launch(void* const* d_in, const int* in_sizes, int n_in,
                              void* d_out, int out_size)
{
    const float* inp   = (const float*)d_in[0];  // [B,T,DI]
    const float* noise = (const float*)d_in[1];  // [B,T,H]
    const float* Wx    = (const float*)d_in[2];  // [H,DI]
    const float* bias  = (const float*)d_in[3];  // [H]
    const float* Wh    = (const float*)d_in[4];  // [H,H]
    const float* Wy    = (const float*)d_in[5];  // [DO,H]
    const float* ah0   = (const float*)d_in[6];  // [H]

    float* out    = (float*)d_out;                  // [B,T,DO] first
    float* hstore = out + (size_t)B_ * T_ * DO_;    // [B,T,H] second

    const int xp_smem = (DI_ * H_ + DI_ * INS_STRIDE) * (int)sizeof(float);  // 67872 B
    static int attr_done = 0;
    if (!attr_done) {
        cudaFuncSetAttribute(xp_gemm_kernel,
                             cudaFuncAttributeMaxDynamicSharedMemorySize, xp_smem);
        attr_done = 1;
    }

    xp_gemm_kernel<<<1024, 256, xp_smem>>>(inp, Wx, bias);
    scan_kernel<<<B_ / 2, 128>>>(noise, Wh, ah0, hstore);
    outproj_kernel<<<(B_ * T_) / 8, 256>>>(hstore, Wy, out);
}